// round 1
// baseline (speedup 1.0000x reference)
#include <cuda_runtime.h>
#include <cuda_bf16.h>
#include <cstdint>

// SimpleSparseConvNet: rulebook sparse conv, Cin=1, Cout=16.
// out[o, 0:16] += feats[i] * W[k, 0, 0:16] for each rulebook pair (i, o, k).
//
// Inputs (metadata order):
//   d_in[0] feats   float32 [N]        (N x Cin, Cin==1)
//   d_in[1] weight  float32 [27*16]    (27 x 1 x 16)
//   d_in[2] in_idx  int32   [M]
//   d_in[3] out_idx int32   [M]
//   d_in[4] k_idx   int32   [M]
//   d_in[5] n_out   (scalar; unused — out_size gives it)
// Output: float32 [n_out * 16]

__device__ __forceinline__ void red_add_v4(float* addr, float a, float b, float c, float d) {
    asm volatile("red.global.add.v4.f32 [%0], {%1, %2, %3, %4};"
                 :: "l"(addr), "f"(a), "f"(b), "f"(c), "f"(d)
                 : "memory");
}

__global__ void __launch_bounds__(256)
sparse_conv_scatter_kernel(const float* __restrict__ feats,
                           const float* __restrict__ weight,
                           const int* __restrict__ in_idx,
                           const int* __restrict__ out_idx,
                           const int* __restrict__ k_idx,
                           float* __restrict__ out,
                           int M) {
    int m = blockIdx.x * blockDim.x + threadIdx.x;
    if (m >= M) return;

    const float f = __ldg(&feats[__ldg(&in_idx[m])]);
    const int k = __ldg(&k_idx[m]);
    const int o = __ldg(&out_idx[m]);

    // Weight row: 16 floats = 4 x float4, 64B aligned (k*16 floats).
    const float4* wp = reinterpret_cast<const float4*>(weight + (size_t)k * 16);
    float* op = out + (size_t)o * 16;

#pragma unroll
    for (int j = 0; j < 4; j++) {
        float4 w = __ldg(&wp[j]);
        red_add_v4(op + j * 4, f * w.x, f * w.y, f * w.z, f * w.w);
    }
}

extern "C" void kernel_launch(void* const* d_in, const int* in_sizes, int n_in,
                              void* d_out, int out_size) {
    const float* feats  = (const float*)d_in[0];
    const float* weight = (const float*)d_in[1];
    const int* in_idx   = (const int*)d_in[2];
    const int* out_idx  = (const int*)d_in[3];
    const int* k_idx    = (const int*)d_in[4];
    float* out = (float*)d_out;

    const int M = in_sizes[2];

    // Output is poisoned to 0xAA by the harness — zero it first.
    cudaMemsetAsync(d_out, 0, (size_t)out_size * sizeof(float), 0);

    const int threads = 256;
    const int blocks = (M + threads - 1) / threads;
    sparse_conv_scatter_kernel<<<blocks, threads>>>(feats, weight, in_idx, out_idx,
                                                    k_idx, out, M);
}